// round 16
// baseline (speedup 1.0000x reference)
#include <cuda_runtime.h>
#include <cstdint>

#define B_   32
#define L_   256
#define T_   1600
#define C_   40
#define PADM 1.0e12f
#define NCH  25          // 25 chunks of 64 t-columns
#define RING 96          // mailbox ring depth (groups)

// ---------------- scratch (__device__ globals; no allocation allowed) ----------------
__device__ __align__(16) float g_coefA[B_ * C_ * L_];   // invvar (scalar)
__device__ __align__(16) float g_coefB[B_ * C_ * L_];   // -2*mu*invvar (scalar)
__device__ __align__(16) float g_t3 [B_ * L_];
__device__ __align__(16) float g_mlv[B_ * L_];
__device__ int g_flag[B_ * NCH];    // lp chunk ready counters (target 2)
__device__ int g_zc;                // alignment-zeroing completion counter

// ---------------- packed f32x2 helpers (sm_103a) ----------------
__device__ __forceinline__ unsigned long long pack2(float lo, float hi) {
    unsigned long long r;
    asm("mov.b64 %0, {%1,%2};" : "=l"(r) : "f"(lo), "f"(hi));
    return r;
}
#define FFMA2_ACC(d, a, b) \
    asm("fma.rn.f32x2 %0, %1, %2, %0;" : "+l"(d) : "l"(a), "l"(b))
#define FFMA2(d, a, b, c) \
    asm("fma.rn.f32x2 %0, %1, %2, %3;" : "=l"(d) : "l"(a), "l"(b), "l"(c))
#define ADD2(d, a, b) \
    asm("add.rn.f32x2 %0, %1, %2;" : "=l"(d) : "l"(a), "l"(b))

// volatile shared accessors
__device__ __forceinline__ uint4 ldsv4v(unsigned a) {
    uint4 r;
    asm volatile("ld.volatile.shared.v4.b32 {%0,%1,%2,%3},[%4];"
                 : "=r"(r.x), "=r"(r.y), "=r"(r.z), "=r"(r.w) : "r"(a));
    return r;
}
__device__ __forceinline__ void stsv4v(unsigned a, uint4 v) {
    asm volatile("st.volatile.shared.v4.b32 [%0],{%1,%2,%3,%4};"
                 :: "r"(a), "r"(v.x), "r"(v.y), "r"(v.z), "r"(v.w));
}
__device__ __forceinline__ int ldsv1v(unsigned a) {
    int r;
    asm volatile("ld.volatile.shared.b32 %0,[%1];" : "=r"(r) : "r"(a));
    return r;
}
__device__ __forceinline__ void stsv1v(unsigned a, int v) {
    asm volatile("st.volatile.shared.b32 [%0],%1;" :: "r"(a), "r"(v));
}
__device__ __forceinline__ void waitflag2(int idx) {
    volatile int* f = g_flag;
    while (f[idx] < 2) {}
    __threadfence();
}

// ---------------- K0: per-(b,l) coefficients + flag reset ----------------
__global__ void k0_coef(const float* __restrict__ mu_logvar) {
    int idx = blockIdx.x * 128 + threadIdx.x;          // 0 .. B*L-1
    if (idx < B_ * NCH) g_flag[idx] = 0;
    if (idx == B_ * NCH) g_zc = 0;
    int b = idx >> 8;
    int l = idx & (L_ - 1);
    const float* row = mu_logvar + (size_t)idx * (2 * C_);
    float* A  = g_coefA + (size_t)b * C_ * L_ + l;
    float* Bc = g_coefB + (size_t)b * C_ * L_ + l;
    float t3 = 0.f, slv = 0.f;
    for (int c = 0; c < C_; c++) {
        float mu = row[c];
        float lv = row[C_ + c];
        float iv = expf(-lv);
        float miv = mu * iv;
        A [c * L_] = iv;
        Bc[c * L_] = -2.0f * miv;
        t3 = fmaf(mu, miv, t3);
        slv += lv;
    }
    g_t3 [idx] = t3;
    g_mlv[idx] = slv * (1.0f / C_);
}

// ---------------- smem layout (fused kernel) ----------------
//   [0, 51200)          D: decision ballot words [T_][8]
//   [51200, 88064)      ring mailbox: 8 warps x 96 slots x 48B
//                       slot: w0{tag=k+1, a0, b0, pad} w1{a1,b1,a2,b2} w2{a3,b3,-,-}
//   [88064, 94464)      b0h[T_]    beta[l=0] history (by t)
//   [94464, 100864)     b255h[T_]  beta[l=255] history (by t)
//   [100864, 107264)    path[T_]
//   [107264, 107268)    shv
//   [107280, 107344)    cons[16]   consumer progress (cons[8..] = MAX)
#define SMB_MB    51200
#define SMB_B0H   88064
#define SMB_B255H 94464
#define SMB_PATH  100864
#define SMB_SHV   107264
#define SMB_CONS  107280
#define SMB_TOT   107360
#define WSTRIDE   4608u    // 96 * 48

// ---- GEMM role: lp for (batch b, half, chunk c) + zero share + publish flag ----
__device__ void k1_role(int b, int half, int c, const float* __restrict__ z,
                        float* __restrict__ lp_out, float* __restrict__ out_align,
                        unsigned char* smraw) {
    float* zs = (float*)smraw;                // [C_][64]
    int t0 = c * 64;
    int tid = threadIdx.x;

    // zero this (b, c, half) share of the alignment output (2048 float4)
    {
        float4* ap = (float4*)(out_align + (size_t)b * T_ * L_) + c * 4096 + half * 2048;
        float4 z4 = make_float4(0.f, 0.f, 0.f, 0.f);
#pragma unroll
        for (int q = 0; q < 8; q++) ap[tid + q * 256] = z4;
    }

    const float* zb = z + (size_t)b * C_ * T_ + t0;
    for (int i = tid; i < C_ * 64; i += 256) {
        int cc = i >> 6, j = i & 63;
        zs[cc * 64 + j] = zb[(size_t)cc * T_ + j];
    }
    __syncthreads();

    int lg = tid >> 3;            // 0..31 -> rows 4lg..4lg+3
    int tg = tid & 7;             // 0..7  -> t cols tg*8..tg*8+7
    int lbase = half * 128 + lg * 4;

    unsigned long long acc[4][4];
#pragma unroll
    for (int r = 0; r < 4; r++)
#pragma unroll
        for (int j = 0; j < 4; j++) acc[r][j] = 0ull;

    const float* cA = g_coefA + (size_t)b * C_ * L_ + lbase;
    const float* cB = g_coefB + (size_t)b * C_ * L_ + lbase;

#pragma unroll 2
    for (int cc = 0; cc < C_; cc++) {
        float4 a4 = *(const float4*)(cA + (size_t)cc * L_);
        float4 b4 = *(const float4*)(cB + (size_t)cc * L_);
        unsigned long long ar[4] = {pack2(a4.x, a4.x), pack2(a4.y, a4.y),
                                    pack2(a4.z, a4.z), pack2(a4.w, a4.w)};
        unsigned long long br[4] = {pack2(b4.x, b4.x), pack2(b4.y, b4.y),
                                    pack2(b4.z, b4.z), pack2(b4.w, b4.w)};
        unsigned long long zp[4];
        {
            const ulonglong2* zrow = (const ulonglong2*)(zs + cc * 64 + tg * 8);
            ulonglong2 w0 = zrow[0], w1 = zrow[1];
            zp[0] = w0.x; zp[1] = w0.y; zp[2] = w1.x; zp[3] = w1.y;
        }
#pragma unroll
        for (int r = 0; r < 4; r++) {
#pragma unroll
            for (int j = 0; j < 4; j++) {
                unsigned long long tmp;
                FFMA2(tmp, ar[r], zp[j], br[r]);     // iv*z + (-2*miv)
                FFMA2_ACC(acc[r][j], tmp, zp[j]);    // acc += (iv*z - 2miv)*z
            }
        }
    }

    float4 t34 = *(const float4*)(g_t3  + b * L_ + lbase);
    float4 mv4 = *(const float4*)(g_mlv + b * L_ + lbase);
    float t3a[4] = {t34.x, t34.y, t34.z, t34.w};
    float mva[4] = {mv4.x, mv4.y, mv4.z, mv4.w};
    unsigned long long c1 = pack2(-0.0125f, -0.0125f);   // -0.5/C
#pragma unroll
    for (int r = 0; r < 4; r++) {
        unsigned long long tp = pack2(t3a[r], t3a[r]);
        unsigned long long dp = pack2(-0.5f * mva[r], -0.5f * mva[r]);
        unsigned long long o[4];
#pragma unroll
        for (int j = 0; j < 4; j++) {
            unsigned long long mse;
            ADD2(mse, acc[r][j], tp);
            FFMA2(o[j], mse, c1, dp);
        }
        float* orow = lp_out + ((size_t)b * L_ + lbase + r) * T_ + t0 + tg * 8;
        ((ulonglong2*)orow)[0] = make_ulonglong2(o[0], o[1]);
        ((ulonglong2*)orow)[1] = make_ulonglong2(o[2], o[3]);
    }

    __threadfence();
    if (tid == 0) {
        atomicAdd(&g_flag[b * NCH + c], 1);
        atomicAdd(&g_zc, 1);
    }
}

// ---- one DP step (t >= 1) ----
__device__ __forceinline__ void gstep(int t, float pre_a, float pre_b,
                                      int lane0, int w,
                                      unsigned* D, float lpv,
                                      float* shv, int mlm1, int tlm1, int l,
                                      float& a, float& bt, float& oA, float& oB) {
    float sa = __shfl_up_sync(0xffffffffu, a, 1);
    float sb = __shfl_up_sync(0xffffffffu, bt, 1);
    float am = lane0 ? pre_a : sa;
    float bm = lane0 ? pre_b : sb;
    unsigned bal = __ballot_sync(0xffffffffu, bm > bt);
    if (lane0) D[(t - 1) * 8 + w] = bal;
    float d = a - am;
    float m = fmaxf(a, am);
    float an = m + __logf(1.0f + __expf(-fabsf(d))) + (lpv + 1e-7f);
    float bn = fmaxf(bt, bm) + lpv;
    if (t == mlm1 && l == tlm1) *shv = an;
    a = an; bt = bn; oA = an; oB = bn;
}

// ---- DP role: 8-warp feed-forward DP, 4-step grouped ring mailbox ----
__device__ void k2_role(int b, const float* __restrict__ lp,
                        const int* __restrict__ tlen, const int* __restrict__ mlen,
                        float* __restrict__ out_loss, float* __restrict__ out_align,
                        unsigned char* smraw) {
    unsigned* D  = (unsigned*)smraw;
    float* b0h   = (float*)(smraw + SMB_B0H);
    float* b255h = (float*)(smraw + SMB_B255H);
    int* path    = (int*)(smraw + SMB_PATH);
    float* shv   = (float*)(smraw + SMB_SHV);
    unsigned smbase = (unsigned)__cvta_generic_to_shared(smraw);
    unsigned mb     = smbase + SMB_MB;
    unsigned consb  = smbase + SMB_CONS;

    int l = threadIdx.x;
    int w = l >> 5, lane = l & 31;
    int lane0 = (lane == 0);
    int lzero = (l == 0);
    int l255  = (l == 255);
    int ml = mlen[b], tl = tlen[b];
    int mlm1 = ml - 1, tlm1 = tl - 1;

    const float* p = lp + ((size_t)b * L_ + l) * T_;
    unsigned mb_self = mb + (unsigned)w * WSTRIDE;
    unsigned mb_src  = mb + (unsigned)(w - 1) * WSTRIDE;   // used only if w>=1
    unsigned cons_self = consb + (unsigned)w * 4u;         // published by consumer warp w
    unsigned cons_next = consb + (unsigned)(w + 1) * 4u;   // checked by producer warp w

    // zero ring tags (2304 uint4) + cons init
    {
        uint4* m4 = (uint4*)(smraw + SMB_MB);
        uint4 zz = make_uint4(0u, 0u, 0u, 0u);
        for (int i = l; i < 2304; i += 256) m4[i] = zz;
        if (l < 16) stsv1v(consb + (unsigned)l * 4u, (l >= 8) ? 0x7FFFFFFF : -1);
    }

    waitflag2(b * NCH + 0);
    float4 vcur = *(const float4*)p;           // quad 0
    float a  = lzero ? vcur.x : -PADM;         // state t=0
    float bt = a;
    __syncthreads();                           // ring zero + cons init visible

    waitflag2(b * NCH + 1);                    // covers chunk-0 prefetch window
    float4 vnext = *(const float4*)(p + 4);

    float ca = -PADM, cb = -PADM;              // carry: w-1 state at t=4k-1
    float pA[4], pB[4];
    int cpv = -1;                              // cached consumer progress (lane31)
    unsigned so_self = 0, so_src = 0;          // ring byte offsets

    // ---- group 0: steps t=1,2,3; entry0 = init state ----
    {
        pA[0] = a; pB[0] = bt;
        float e0a = -PADM, e0b = -PADM, e1a = -PADM, e1b = -PADM,
              e2a = -PADM, e2b = -PADM;
        if (w) {
            unsigned sl = mb_src;
            uint4 s0 = ldsv4v(sl);
            while (s0.x != 1u) s0 = ldsv4v(sl);
            uint4 s1 = ldsv4v(sl + 16u);
            uint4 s2 = ldsv4v(sl + 32u);
            e0a = __uint_as_float(s0.y); e0b = __uint_as_float(s0.z);
            e1a = __uint_as_float(s1.x); e1b = __uint_as_float(s1.y);
            e2a = __uint_as_float(s1.z); e2b = __uint_as_float(s1.w);
            ca  = __uint_as_float(s2.x); cb  = __uint_as_float(s2.y);
            if (lane0) stsv1v(cons_self, 0);
        }
        gstep(1, e0a, e0b, lane0, w, D, vcur.y, shv, mlm1, tlm1, l, a, bt, pA[1], pB[1]);
        gstep(2, e1a, e1b, lane0, w, D, vcur.z, shv, mlm1, tlm1, l, a, bt, pA[2], pB[2]);
        gstep(3, e2a, e2b, lane0, w, D, vcur.w, shv, mlm1, tlm1, l, a, bt, pA[3], pB[3]);
        if (lane == 31) {
            stsv4v(mb_self + 32u, make_uint4(__float_as_uint(pA[3]), __float_as_uint(pB[3]), 0u, 0u));
            stsv4v(mb_self + 16u, make_uint4(__float_as_uint(pA[1]), __float_as_uint(pB[1]),
                                             __float_as_uint(pA[2]), __float_as_uint(pB[2])));
            stsv4v(mb_self,       make_uint4(1u, __float_as_uint(pA[0]), __float_as_uint(pB[0]), 0u));
        }
        if (lzero)
            stsv4v(smbase + SMB_B0H, make_uint4(__float_as_uint(pB[0]), __float_as_uint(pB[1]),
                                                __float_as_uint(pB[2]), __float_as_uint(pB[3])));
        if (l255)
            stsv4v(smbase + SMB_B255H, make_uint4(__float_as_uint(pB[0]), __float_as_uint(pB[1]),
                                                  __float_as_uint(pB[2]), __float_as_uint(pB[3])));
        vcur = vnext; vnext = *(const float4*)(p + 8);
    }

    // ---- groups 1..399 ----
    for (int k = 1; k < 400; k++) {
        so_self += 48u; if (so_self == WSTRIDE) so_self = 0u;
        so_src  += 48u; if (so_src  == WSTRIDE) so_src  = 0u;
        if ((k & 15) == 0) {
            int c2 = (k >> 4) + 1;
            waitflag2(b * NCH + (c2 < NCH ? c2 : NCH - 1));
        }
        float4 vf = (k + 2 < 400) ? *(const float4*)(p + 4 * (k + 2)) : vcur;
        float e0a = -PADM, e0b = -PADM, e1a = -PADM, e1b = -PADM,
              e2a = -PADM, e2b = -PADM, nca = -PADM, ncb = -PADM;
        if (w) {
            unsigned sl = mb_src + so_src;
            uint4 s0 = ldsv4v(sl);
            while (s0.x != (unsigned)(k + 1)) s0 = ldsv4v(sl);
            uint4 s1 = ldsv4v(sl + 16u);
            uint4 s2 = ldsv4v(sl + 32u);
            e0a = __uint_as_float(s0.y); e0b = __uint_as_float(s0.z);
            e1a = __uint_as_float(s1.x); e1b = __uint_as_float(s1.y);
            e2a = __uint_as_float(s1.z); e2b = __uint_as_float(s1.w);
            nca = __uint_as_float(s2.x); ncb = __uint_as_float(s2.y);
            if (lane0) stsv1v(cons_self, k);
        }
        int t0 = 4 * k;
        gstep(t0,     ca,  cb,  lane0, w, D, vcur.x, shv, mlm1, tlm1, l, a, bt, pA[0], pB[0]);
        gstep(t0 + 1, e0a, e0b, lane0, w, D, vcur.y, shv, mlm1, tlm1, l, a, bt, pA[1], pB[1]);
        gstep(t0 + 2, e1a, e1b, lane0, w, D, vcur.z, shv, mlm1, tlm1, l, a, bt, pA[2], pB[2]);
        gstep(t0 + 3, e2a, e2b, lane0, w, D, vcur.w, shv, mlm1, tlm1, l, a, bt, pA[3], pB[3]);
        ca = nca; cb = ncb;
        if (lane == 31) {
            // backpressure: slot for group k reused from group k-RING
            if (cpv < k - RING) { do { cpv = ldsv1v(cons_next); } while (cpv < k - RING); }
            unsigned sl = mb_self + so_self;
            stsv4v(sl + 32u, make_uint4(__float_as_uint(pA[3]), __float_as_uint(pB[3]), 0u, 0u));
            stsv4v(sl + 16u, make_uint4(__float_as_uint(pA[1]), __float_as_uint(pB[1]),
                                        __float_as_uint(pA[2]), __float_as_uint(pB[2])));
            stsv4v(sl,       make_uint4((unsigned)(k + 1), __float_as_uint(pA[0]),
                                        __float_as_uint(pB[0]), 0u));
        }
        if (lzero)
            stsv4v(smbase + SMB_B0H + (unsigned)k * 16u,
                   make_uint4(__float_as_uint(pB[0]), __float_as_uint(pB[1]),
                              __float_as_uint(pB[2]), __float_as_uint(pB[3])));
        if (l255)
            stsv4v(smbase + SMB_B255H + (unsigned)k * 16u,
                   make_uint4(__float_as_uint(pB[0]), __float_as_uint(pB[1]),
                              __float_as_uint(pB[2]), __float_as_uint(pB[3])));
        vcur = vnext; vnext = vf;
    }

    // ---- column T-1 = 1599 decision bits (uses final carry) ----
    {
        float sb = __shfl_up_sync(0xffffffffu, bt, 1);
        float bm = lane0 ? cb : sb;               // w==0 lane0 fixed below
        unsigned bal = __ballot_sync(0xffffffffu, bm > bt);
        if (lane0) D[(T_ - 1) * 8 + w] = bal;
    }
    __syncthreads();

    // ---- wrap fixup: bit0 of D[c*8] = (beta[255,c] > beta[0,c]) ----
    for (int c = l; c < T_; c += 256) {
        unsigned wv = D[c * 8];
        wv = (wv & ~1u) | ((b255h[c] > b0h[c]) ? 1u : 0u);
        D[c * 8] = wv;
    }
    __syncthreads();

    // serial backtrack (exact emulation of reference relu/mod arithmetic)
    if (l == 0) {
        out_loss[b] = -(*shv) / (float)ml;
        int rows = tlm1, cols = mlm1;
        path[0] = rows;
        for (int k = 1; k < ml; k++) {
            int col = ((cols - 1) % T_ + T_) % T_;
            int br_ = rows & (L_ - 1);
            unsigned wv = D[col * 8 + (br_ >> 5)];
            int is_go = (wv >> (br_ & 31)) & 1;
            int tmp = rows - is_go + 1;
            rows = (tmp > 0 ? tmp : 0) - 1;
            cols = (cols > 0 ? cols : 0) - 1;
            path[k] = rows;
        }
        // all alignment-zeroing shares must be done before one-hot writes
        volatile int* zc = &g_zc;
        while (*zc != 2 * B_ * NCH) {}
        __threadfence();
    }
    __syncthreads();

    // write one-hot ones: final[t] = onehot(path[ml-1-t]) for t < ml
    size_t abase = (size_t)b * T_ * L_;
    for (int t = l; t < ml; t += 256) {
        int r = path[mlm1 - t];
        if (r >= 0) out_align[abase + (size_t)t * L_ + r] = 1.0f;
    }
}

__global__ __launch_bounds__(256, 2) void k12_fused(const float* __restrict__ z,
                                                    float* __restrict__ lp_out,
                                                    const int* __restrict__ tlen,
                                                    const int* __restrict__ mlen,
                                                    float* __restrict__ out_loss,
                                                    float* __restrict__ out_align) {
    extern __shared__ unsigned char smraw[];
    if (blockIdx.x < B_) {
        k2_role(blockIdx.x, lp_out, tlen, mlen, out_loss, out_align, smraw);
    } else {
        int i = blockIdx.x - B_;
        int b = i & (B_ - 1);          // batch fastest
        int half = (i >> 5) & 1;
        int c = i >> 6;                // chunk slowest -> chunk 0 all batches first
        k1_role(b, half, c, z, lp_out, out_align, smraw);
    }
}

// ---------------- launch ----------------
extern "C" void kernel_launch(void* const* d_in, const int* in_sizes, int n_in,
                              void* d_out, int out_size) {
    const float* mu_logvar = (const float*)d_in[0];   // [B, L, 2C]
    const float* z         = (const float*)d_in[1];   // [B, C, T]
    const int*   tlen      = (const int*)d_in[2];     // [B]
    const int*   mlen      = (const int*)d_in[3];     // [B]

    float* out       = (float*)d_out;
    float* out_loss  = out;                                   // [B]
    float* out_align = out + B_;                              // [B, T, L]
    float* out_lp    = out_align + (size_t)B_ * T_ * L_;      // [B, L, T]

    cudaFuncSetAttribute(k12_fused, cudaFuncAttributeMaxDynamicSharedMemorySize,
                         SMB_TOT);

    k0_coef<<<(B_ * L_) / 128, 128>>>(mu_logvar);
    k12_fused<<<B_ + 2 * B_ * NCH, 256, SMB_TOT>>>(z, out_lp, tlen, mlen,
                                                   out_loss, out_align);
}